// round 13
// baseline (speedup 1.0000x reference)
#include <cuda_runtime.h>
#include <cuda_bf16.h>
#include <cuda_fp8.h>
#include <cstdint>

// ============================================================================
// y[M,N] = fq(x*sx)[M,K] @ fq(w*sw)[N,K]^T / (sx*sw) + bias, bf16-rounded,
// stored as f32. fp8 mma.sync.m16n8k32 (bit-exact, R9+).
// R13: R11 skeleton (correct cp.async visibility: wait -> barrier -> read)
// + register double-buffered fragments to hide LDSM latency inside the chunk.
// ============================================================================
#define GM 8192
#define GN 4096
#define GK 4096

#define BM 128
#define BN 128
#define BK 128                     // fp8 bytes (= elems) per K chunk
#define K_CHUNKS (GK / BK)         // 32
#define STAGES 3
#define THREADS 256

#define A_BYTES (BM * BK)          // 16384
#define B_BYTES (BN * BK)          // 16384
#define STAGE_BYTES (A_BYTES + B_BYTES)      // 32768
#define SMEM_TOTAL (STAGES * STAGE_BYTES)    // 98304 -> 2 CTAs/SM

// fp8 scratch, plain row-major [M][K] / [N][K]
__device__ __align__(128) unsigned char g_Aq[(size_t)GM * GK];
__device__ __align__(128) unsigned char g_Bq[(size_t)GN * GK];

// ============================================================================
// helpers
// ============================================================================
__device__ __forceinline__ uint32_t smem_to_u32(const void* p) {
    uint32_t a;
    asm("{ .reg .u64 t; cvta.to.shared.u64 t, %1; cvt.u32.u64 %0, t; }" : "=r"(a) : "l"(p));
    return a;
}
__device__ __forceinline__ void cp_async16(uint32_t dst_smem, const void* src) {
    asm volatile("cp.async.cg.shared.global [%0], [%1], 16;"
                 :: "r"(dst_smem), "l"(src) : "memory");
}
#define CP_COMMIT() asm volatile("cp.async.commit_group;" ::: "memory")
#define CP_WAIT1()  asm volatile("cp.async.wait_group 1;" ::: "memory")
#define CP_WAIT0()  asm volatile("cp.async.wait_group 0;" ::: "memory")

__device__ __forceinline__ void ldmatrix_x4(uint32_t& r0, uint32_t& r1,
                                            uint32_t& r2, uint32_t& r3, uint32_t addr) {
    asm volatile("ldmatrix.sync.aligned.m8n8.x4.shared.b16 {%0,%1,%2,%3}, [%4];"
                 : "=r"(r0), "=r"(r1), "=r"(r2), "=r"(r3) : "r"(addr));
}

__device__ __forceinline__ void mma_e4m3(float* d, const uint32_t* a,
                                         uint32_t b0, uint32_t b1) {
    asm volatile(
        "mma.sync.aligned.m16n8k32.row.col.f32.e4m3.e4m3.f32 "
        "{%0,%1,%2,%3}, {%4,%5,%6,%7}, {%8,%9}, {%0,%1,%2,%3};"
        : "+f"(d[0]), "+f"(d[1]), "+f"(d[2]), "+f"(d[3])
        : "r"(a[0]), "r"(a[1]), "r"(a[2]), "r"(a[3]), "r"(b0), "r"(b1));
}

// ----------------------------------------------------------------------------
// Exact reference fake-quant (E4M3). Bit-exact vs reference (R8-R11: rel=0).
// ----------------------------------------------------------------------------
__device__ __forceinline__ float fake_quant_e4m3(float y) {
    float yc = fminf(fmaxf(y, -448.0f), 448.0f);
    float mag = fabsf(yc);
    if (mag == 0.0f) return 0.0f;
    int e = (int)((__float_as_uint(mag) >> 23) & 0xFF) - 127;
    if (e < -6) e = -6;
    float stepinv = __int_as_float((uint32_t)(127 + 3 - e) << 23);  // 2^(3-e)
    float step    = __int_as_float((uint32_t)(127 - 3 + e) << 23);  // 2^(e-3)
    return rintf(yc * stepinv) * step;
}

// ============================================================================
// Merged quantization: one launch covers both x (-> g_Aq) and w (-> g_Bq).
// ============================================================================
#define X_TOTAL8 (GM * GK / 8)     // 4,194,304
#define W_TOTAL8 (GN * GK / 8)     // 2,097,152

__global__ void quant_both_kernel(const float* __restrict__ x,
                                  const float* __restrict__ wgt,
                                  const float* __restrict__ xs,
                                  const float* __restrict__ ws) {
    int idx = blockIdx.x * blockDim.x + threadIdx.x;
    const float* src;
    unsigned char* dst;
    float s;
    if (idx < X_TOTAL8) {
        src = x; dst = g_Aq; s = xs[0];
    } else {
        idx -= X_TOTAL8;
        if (idx >= W_TOTAL8) return;
        src = wgt; dst = g_Bq; s = ws[0];
    }
    size_t e0 = (size_t)idx * 8;
    float4 v0 = *reinterpret_cast<const float4*>(src + e0);
    float4 v1 = *reinterpret_cast<const float4*>(src + e0 + 4);
    float f[8] = {v0.x, v0.y, v0.z, v0.w, v1.x, v1.y, v1.z, v1.w};
    uint64_t out8 = 0;
#pragma unroll
    for (int i = 0; i < 8; i++) {
        float q = fake_quant_e4m3(f[i] * s);
        uint8_t b = __nv_cvt_float_to_fp8(q, __NV_SATFINITE, __NV_E4M3);
        out8 |= (uint64_t)b << (8 * i);
    }
    *reinterpret_cast<uint64_t*>(dst + e0) = out8;
}

// ============================================================================
// FP8 GEMM: 128x128 CTA tile, 8 warps (32x64 each), 3-stage pipeline,
// 2 CTAs/SM; per-ks fragment double-buffering inside the chunk.
// ============================================================================
__global__ void __launch_bounds__(THREADS, 2) gemm_kernel(
    const float* __restrict__ bias,
    const float* __restrict__ xs, const float* __restrict__ ws,
    float* __restrict__ out) {
    extern __shared__ __align__(128) char smem[];
    const uint32_t smem_base = smem_to_u32(smem);
    const int tid = threadIdx.x;
    const int w = tid >> 5, l = tid & 31;
    const int warp_m = (w >> 1) * 32;     // 0,32,64,96
    const int warp_n = (w & 1) * 64;      // 0,64
    const int nt = blockIdx.x, mt = blockIdx.y;

    const unsigned char* Ag = g_Aq + (size_t)(mt * BM) * GK;
    const unsigned char* Bg = g_Bq + (size_t)(nt * BN) * GK;

    auto load_stage = [&](int s, int kc) {
        const uint32_t sa = smem_base + s * STAGE_BYTES;
        const uint32_t sb = sa + A_BYTES;
#pragma unroll
        for (int i = 0; i < 4; i++) {
            int c = tid + i * THREADS;
            int row = c >> 3, cb = c & 7;
            cp_async16(sa + row * 128 + ((cb ^ (row & 7)) << 4),
                       Ag + (size_t)row * GK + kc * BK + cb * 16);
        }
#pragma unroll
        for (int i = 0; i < 4; i++) {
            int c = tid + i * THREADS;
            int row = c >> 3, cb = c & 7;
            cp_async16(sb + row * 128 + ((cb ^ (row & 7)) << 4),
                       Bg + (size_t)row * GK + kc * BK + cb * 16);
        }
        CP_COMMIT();
    };

    // accumulators: [mi 0..1][n8-tile 0..7][4]  = 64 regs
    float d[2][8][4];
#pragma unroll
    for (int i = 0; i < 2; i++)
#pragma unroll
        for (int j = 0; j < 8; j++)
#pragma unroll
            for (int q = 0; q < 4; q++) d[i][j][q] = 0.0f;

    load_stage(0, 0);
    load_stage(1, 1);

    const int lr = l & 15;        // ldmatrix row-within-16
    const int lk = l >> 4;        // ldmatrix k-half (16B group select)
    const int rowA0 = (warp_m + lr) * 128;
    const int rowB0 = (warp_n + lr) * 128;
    const int rxA = (warp_m + lr) & 7;
    const int rxB = (warp_n + lr) & 7;

    // fragment double buffers: a[2][2][4] + bf[2][4][4] = 48 regs
    uint32_t a[2][2][4], bf[2][4][4];

    auto load_frags = [&](uint32_t sa, uint32_t sb, int ks, int buf) {
        const int kg = ks * 2 + lk;
        const int colA = ((kg ^ rxA) & 7) << 4;
        const int colB = ((kg ^ rxB) & 7) << 4;
#pragma unroll
        for (int mi = 0; mi < 2; mi++)
            ldmatrix_x4(a[buf][mi][0], a[buf][mi][1], a[buf][mi][2], a[buf][mi][3],
                        sa + rowA0 + mi * (16 * 128) + colA);
#pragma unroll
        for (int j = 0; j < 4; j++)
            ldmatrix_x4(bf[buf][j][0], bf[buf][j][1], bf[buf][j][2], bf[buf][j][3],
                        sb + rowB0 + j * (16 * 128) + colB);
    };

#pragma unroll 1
    for (int kc = 0; kc < K_CHUNKS; ++kc) {
        CP_WAIT1();               // own groups for chunk kc complete
        __syncthreads();          // all threads' copies visible; stage reload safe
        if (kc + 2 < K_CHUNKS) load_stage((kc + 2) % STAGES, kc + 2);

        const int s = kc % STAGES;
        const uint32_t sa = smem_base + s * STAGE_BYTES;
        const uint32_t sb = sa + A_BYTES;

        load_frags(sa, sb, 0, 0);
#pragma unroll
        for (int ks = 0; ks < 4; ++ks) {
            const int cur = ks & 1;
            if (ks < 3) load_frags(sa, sb, ks + 1, cur ^ 1);   // prefetch next ks
#pragma unroll
            for (int mi = 0; mi < 2; mi++)
#pragma unroll
                for (int nj = 0; nj < 8; nj++) {
                    const int j = nj >> 1, h = nj & 1;
                    mma_e4m3(d[mi][nj], a[cur][mi], bf[cur][j][h], bf[cur][j][2 + h]);
                }
        }
    }
    CP_WAIT0();

    // ---- epilogue: dequant + bias, bf16-round, f32 stores ----
    const float inv = 1.0f / (xs[0] * ws[0]);
    const int mrow = mt * BM + warp_m + (l >> 2);
    const int ncol0 = nt * BN + warp_n + 2 * (l & 3);

#pragma unroll
    for (int nj = 0; nj < 8; nj++) {
        const int n = ncol0 + nj * 8;
        const float b0 = bias[n];
        const float b1 = bias[n + 1];
#pragma unroll
        for (int mi = 0; mi < 2; mi++) {
            const int m0 = mrow + mi * 16;
            float f0 = __bfloat162float(__float2bfloat16_rn(d[mi][nj][0] * inv + b0));
            float f1 = __bfloat162float(__float2bfloat16_rn(d[mi][nj][1] * inv + b1));
            float f2 = __bfloat162float(__float2bfloat16_rn(d[mi][nj][2] * inv + b0));
            float f3 = __bfloat162float(__float2bfloat16_rn(d[mi][nj][3] * inv + b1));
            *reinterpret_cast<float2*>(out + (size_t)m0 * GN + n) = make_float2(f0, f1);
            *reinterpret_cast<float2*>(out + (size_t)(m0 + 8) * GN + n) = make_float2(f2, f3);
        }
    }
}

// ============================================================================
// kernel_launch — inputs identified by element count
// ============================================================================
extern "C" void kernel_launch(void* const* d_in, const int* in_sizes, int n_in,
                              void* d_out, int out_size) {
    const float* x = nullptr;
    const float* wgt = nullptr;
    const float* bias = nullptr;
    const float* scales[3] = {nullptr, nullptr, nullptr};
    int ns = 0;
    for (int i = 0; i < n_in; i++) {
        const int sz = in_sizes[i];
        if (sz == GM * GK)      x    = (const float*)d_in[i];
        else if (sz == GN * GK) wgt  = (const float*)d_in[i];
        else if (sz == GN)      bias = (const float*)d_in[i];
        else if (sz == 1 && ns < 3) scales[ns++] = (const float*)d_in[i];
    }
    const float* xs = scales[0];   // x_scale (first size-1 input)
    const float* ws = scales[1];   // w_scale (second size-1 input)
    float* out = (float*)d_out;

    {
        const int total = X_TOTAL8 + W_TOTAL8;          // 6,291,456 threads
        quant_both_kernel<<<total / 256, 256>>>(x, wgt, xs, ws);
    }

    cudaFuncSetAttribute(gemm_kernel, cudaFuncAttributeMaxDynamicSharedMemorySize, SMEM_TOTAL);
    dim3 grid(GN / BN, GM / BM);   // (32, 64) = 2048 CTAs, 2/SM
    gemm_kernel<<<grid, THREADS, SMEM_TOTAL>>>(bias, xs, ws, out);
}

// round 15
// speedup vs baseline: 1.0130x; 1.0130x over previous
#include <cuda_runtime.h>
#include <cuda_bf16.h>
#include <cuda_fp8.h>
#include <cstdint>

// ============================================================================
// y[M,N] = fq(x*sx)[M,K] @ fq(w*sw)[N,K]^T / (sx*sw) + bias, bf16-rounded,
// stored as f32. fp8 mma.sync.m16n8k32 (bit-exact, R9+).
// R15: R14 mbarrier pipeline with the cp.async.mbarrier.arrive.NOINC fix
// (default form is net-zero on the barrier -> R14 deadlock). No __syncthreads
// in the mainloop; full[s]/empty[s] mbarriers pace a 3-stage pipeline.
// ============================================================================
#define GM 8192
#define GN 4096
#define GK 4096

#define BM 128
#define BN 128
#define BK 128                     // fp8 bytes per K chunk
#define K_CHUNKS (GK / BK)         // 32
#define STAGES 3
#define THREADS 256

#define A_BYTES (BM * BK)          // 16384
#define B_BYTES (BN * BK)          // 16384
#define STAGE_BYTES (A_BYTES + B_BYTES)      // 32768
#define STAGE_SMEM (STAGES * STAGE_BYTES)    // 98304
#define SMEM_TOTAL (STAGE_SMEM + 64)         // + mbarriers; 2 CTAs/SM

// fp8 scratch, plain row-major [M][K] / [N][K]
__device__ __align__(128) unsigned char g_Aq[(size_t)GM * GK];
__device__ __align__(128) unsigned char g_Bq[(size_t)GN * GK];

// ============================================================================
// helpers
// ============================================================================
__device__ __forceinline__ uint32_t smem_to_u32(const void* p) {
    uint32_t a;
    asm("{ .reg .u64 t; cvta.to.shared.u64 t, %1; cvt.u32.u64 %0, t; }" : "=r"(a) : "l"(p));
    return a;
}
__device__ __forceinline__ void cp_async16(uint32_t dst_smem, const void* src) {
    asm volatile("cp.async.cg.shared.global [%0], [%1], 16;"
                 :: "r"(dst_smem), "l"(src) : "memory");
}

#define MBARRIER_INIT(addr, cnt) \
    asm volatile("mbarrier.init.shared.b64 [%0], %1;" \
                 :: "r"((uint32_t)(addr)), "r"((uint32_t)(cnt)) : "memory")
#define MBARRIER_ARRIVE(addr) \
    asm volatile("mbarrier.arrive.shared.b64 _, [%0];" :: "r"((uint32_t)(addr)) : "memory")
// NOINC: this thread's pending cp.asyncs perform ONE real arrive on completion
// (default form increments pend-count first -> net zero -> deadlock, R14).
#define CP_ASYNC_MBAR_ARRIVE_NOINC(addr) \
    asm volatile("cp.async.mbarrier.arrive.noinc.shared.b64 [%0];" \
                 :: "r"((uint32_t)(addr)) : "memory")

#define MBAR_WAIT(mbar, parity) do { \
    uint32_t _m = (uint32_t)(mbar); \
    uint32_t _p = (uint32_t)(parity); \
    uint32_t _done; \
    asm volatile("{\n\t.reg .pred p;\n\t" \
        "mbarrier.try_wait.parity.acquire.cta.shared::cta.b64 p, [%1], %2;\n\t" \
        "selp.b32 %0, 1, 0, p;\n\t}" : "=r"(_done) : "r"(_m), "r"(_p) : "memory"); \
    if (!_done) { \
        asm volatile("{\n\t.reg .pred P1;\n\t" \
            "WL_%=:\n\t" \
            "mbarrier.try_wait.parity.acquire.cta.shared::cta.b64 P1, [%0], %1, 0x989680;\n\t" \
            "@P1 bra.uni WD_%=;\n\t" \
            "bra.uni WL_%=;\n\t" \
            "WD_%=:\n\t}" :: "r"(_m), "r"(_p) : "memory"); \
    } \
} while (0)

__device__ __forceinline__ void ldmatrix_x4(uint32_t& r0, uint32_t& r1,
                                            uint32_t& r2, uint32_t& r3, uint32_t addr) {
    asm volatile("ldmatrix.sync.aligned.m8n8.x4.shared.b16 {%0,%1,%2,%3}, [%4];"
                 : "=r"(r0), "=r"(r1), "=r"(r2), "=r"(r3) : "r"(addr));
}

__device__ __forceinline__ void mma_e4m3(float* d, const uint32_t* a,
                                         uint32_t b0, uint32_t b1) {
    asm volatile(
        "mma.sync.aligned.m16n8k32.row.col.f32.e4m3.e4m3.f32 "
        "{%0,%1,%2,%3}, {%4,%5,%6,%7}, {%8,%9}, {%0,%1,%2,%3};"
        : "+f"(d[0]), "+f"(d[1]), "+f"(d[2]), "+f"(d[3])
        : "r"(a[0]), "r"(a[1]), "r"(a[2]), "r"(a[3]), "r"(b0), "r"(b1));
}

// ----------------------------------------------------------------------------
// Exact reference fake-quant (E4M3). Bit-exact vs reference (R8-R13: rel=0).
// ----------------------------------------------------------------------------
__device__ __forceinline__ float fake_quant_e4m3(float y) {
    float yc = fminf(fmaxf(y, -448.0f), 448.0f);
    float mag = fabsf(yc);
    if (mag == 0.0f) return 0.0f;
    int e = (int)((__float_as_uint(mag) >> 23) & 0xFF) - 127;
    if (e < -6) e = -6;
    float stepinv = __int_as_float((uint32_t)(127 + 3 - e) << 23);  // 2^(3-e)
    float step    = __int_as_float((uint32_t)(127 - 3 + e) << 23);  // 2^(e-3)
    return rintf(yc * stepinv) * step;
}

// ============================================================================
// Merged quantization: one launch covers both x (-> g_Aq) and w (-> g_Bq).
// ============================================================================
#define X_TOTAL8 (GM * GK / 8)
#define W_TOTAL8 (GN * GK / 8)

__global__ void quant_both_kernel(const float* __restrict__ x,
                                  const float* __restrict__ wgt,
                                  const float* __restrict__ xs,
                                  const float* __restrict__ ws) {
    int idx = blockIdx.x * blockDim.x + threadIdx.x;
    const float* src;
    unsigned char* dst;
    float s;
    if (idx < X_TOTAL8) {
        src = x; dst = g_Aq; s = xs[0];
    } else {
        idx -= X_TOTAL8;
        if (idx >= W_TOTAL8) return;
        src = wgt; dst = g_Bq; s = ws[0];
    }
    size_t e0 = (size_t)idx * 8;
    float4 v0 = *reinterpret_cast<const float4*>(src + e0);
    float4 v1 = *reinterpret_cast<const float4*>(src + e0 + 4);
    float f[8] = {v0.x, v0.y, v0.z, v0.w, v1.x, v1.y, v1.z, v1.w};
    uint64_t out8 = 0;
#pragma unroll
    for (int i = 0; i < 8; i++) {
        float q = fake_quant_e4m3(f[i] * s);
        uint8_t b = __nv_cvt_float_to_fp8(q, __NV_SATFINITE, __NV_E4M3);
        out8 |= (uint64_t)b << (8 * i);
    }
    *reinterpret_cast<uint64_t*>(dst + e0) = out8;
}

// ============================================================================
// FP8 GEMM: 128x128 CTA tile, 8 warps (32x64), 3-stage mbarrier pipeline,
// 2 CTAs/SM. No block-wide barrier in the mainloop.
// ============================================================================
__global__ void __launch_bounds__(THREADS, 2) gemm_kernel(
    const float* __restrict__ bias,
    const float* __restrict__ xs, const float* __restrict__ ws,
    float* __restrict__ out) {
    extern __shared__ __align__(128) char smem[];
    const uint32_t smem_base = smem_to_u32(smem);
    const uint32_t mbar_base = smem_base + STAGE_SMEM;   // full[s]@+16s, empty[s]@+16s+8
    const int tid = threadIdx.x;
    const int w = tid >> 5, l = tid & 31;
    const int warp_m = (w >> 1) * 32;     // 0,32,64,96
    const int warp_n = (w & 1) * 64;      // 0,64
    const int nt = blockIdx.x, mt = blockIdx.y;

    if (tid == 0) {
#pragma unroll
        for (int s = 0; s < STAGES; s++) {
            MBARRIER_INIT(mbar_base + 16 * s, THREADS);      // full[s]
            MBARRIER_INIT(mbar_base + 16 * s + 8, THREADS);  // empty[s]
        }
    }
    __syncthreads();   // inits visible; only block-wide barrier in the kernel

    const unsigned char* Ag = g_Aq + (size_t)(mt * BM) * GK;
    const unsigned char* Bg = g_Bq + (size_t)(nt * BN) * GK;

    // produce chunk kc into stage s (s = kc % STAGES, u = kc / STAGES passed in)
    auto produce = [&](int kc, int s, int u) {
        if (kc >= STAGES) {
            MBAR_WAIT(mbar_base + 16 * s + 8, (u - 1) & 1);  // prior use consumed
        }
        const uint32_t sa = smem_base + s * STAGE_BYTES;
        const uint32_t sb = sa + A_BYTES;
#pragma unroll
        for (int i = 0; i < 4; i++) {
            int c = tid + i * THREADS;
            int row = c >> 3, cb = c & 7;
            cp_async16(sa + row * 128 + ((cb ^ (row & 7)) << 4),
                       Ag + (size_t)row * GK + kc * BK + cb * 16);
        }
#pragma unroll
        for (int i = 0; i < 4; i++) {
            int c = tid + i * THREADS;
            int row = c >> 3, cb = c & 7;
            cp_async16(sb + row * 128 + ((cb ^ (row & 7)) << 4),
                       Bg + (size_t)row * GK + kc * BK + cb * 16);
        }
        CP_ASYNC_MBAR_ARRIVE_NOINC(mbar_base + 16 * s);      // 1 real arrive on completion
    };

    // accumulators: [mi 0..1][n8-tile 0..7][4]  = 64 regs
    float d[2][8][4];
#pragma unroll
    for (int i = 0; i < 2; i++)
#pragma unroll
        for (int j = 0; j < 8; j++)
#pragma unroll
            for (int q = 0; q < 4; q++) d[i][j][q] = 0.0f;

    produce(0, 0, 0);
    produce(1, 1, 0);

    const int lr = l & 15;
    const int lk = l >> 4;
    const int rowA0 = (warp_m + lr) * 128;
    const int rowB0 = (warp_n + lr) * 128;
    const int rxA = (warp_m + lr) & 7;
    const int rxB = (warp_n + lr) & 7;

    // rolling counters (avoid % and / in the hot loop)
    int s_cons = 0, u_cons = 0;           // consumer stage + use-index
    int s_prod = 2, u_prod = 0;           // producer stage (for kc+2) + use-index

#pragma unroll 1
    for (int kc = 0; kc < K_CHUNKS; ++kc) {
        if (kc + 2 < K_CHUNKS) {
            produce(kc + 2, s_prod, u_prod);
            if (++s_prod == STAGES) { s_prod = 0; ++u_prod; }
        }

        MBAR_WAIT(mbar_base + 16 * s_cons, u_cons & 1);      // stage full

        const uint32_t sa = smem_base + s_cons * STAGE_BYTES;
        const uint32_t sb = sa + A_BYTES;

#pragma unroll
        for (int ks = 0; ks < 4; ++ks) {
            uint32_t a[2][4], bf[4][4];
            const int kg = ks * 2 + lk;
            const int colA = ((kg ^ rxA) & 7) << 4;
            const int colB = ((kg ^ rxB) & 7) << 4;
#pragma unroll
            for (int mi = 0; mi < 2; mi++)
                ldmatrix_x4(a[mi][0], a[mi][1], a[mi][2], a[mi][3],
                            sa + rowA0 + mi * (16 * 128) + colA);
#pragma unroll
            for (int j = 0; j < 4; j++)
                ldmatrix_x4(bf[j][0], bf[j][1], bf[j][2], bf[j][3],
                            sb + rowB0 + j * (16 * 128) + colB);
#pragma unroll
            for (int mi = 0; mi < 2; mi++)
#pragma unroll
                for (int nj = 0; nj < 8; nj++) {
                    const int j = nj >> 1, h = nj & 1;
                    mma_e4m3(d[mi][nj], a[mi], bf[j][h], bf[j][2 + h]);
                }
        }
        MBARRIER_ARRIVE(mbar_base + 16 * s_cons + 8);        // stage empty (this thread)
        if (++s_cons == STAGES) { s_cons = 0; ++u_cons; }
    }

    // ---- epilogue: dequant + bias, bf16-round, f32 stores ----
    const float inv = 1.0f / (xs[0] * ws[0]);
    const int mrow = mt * BM + warp_m + (l >> 2);
    const int ncol0 = nt * BN + warp_n + 2 * (l & 3);

#pragma unroll
    for (int nj = 0; nj < 8; nj++) {
        const int n = ncol0 + nj * 8;
        const float b0 = bias[n];
        const float b1 = bias[n + 1];
#pragma unroll
        for (int mi = 0; mi < 2; mi++) {
            const int m0 = mrow + mi * 16;
            float f0 = __bfloat162float(__float2bfloat16_rn(d[mi][nj][0] * inv + b0));
            float f1 = __bfloat162float(__float2bfloat16_rn(d[mi][nj][1] * inv + b1));
            float f2 = __bfloat162float(__float2bfloat16_rn(d[mi][nj][2] * inv + b0));
            float f3 = __bfloat162float(__float2bfloat16_rn(d[mi][nj][3] * inv + b1));
            *reinterpret_cast<float2*>(out + (size_t)m0 * GN + n) = make_float2(f0, f1);
            *reinterpret_cast<float2*>(out + (size_t)(m0 + 8) * GN + n) = make_float2(f2, f3);
        }
    }
}

// ============================================================================
// kernel_launch — inputs identified by element count
// ============================================================================
extern "C" void kernel_launch(void* const* d_in, const int* in_sizes, int n_in,
                              void* d_out, int out_size) {
    const float* x = nullptr;
    const float* wgt = nullptr;
    const float* bias = nullptr;
    const float* scales[3] = {nullptr, nullptr, nullptr};
    int ns = 0;
    for (int i = 0; i < n_in; i++) {
        const int sz = in_sizes[i];
        if (sz == GM * GK)      x    = (const float*)d_in[i];
        else if (sz == GN * GK) wgt  = (const float*)d_in[i];
        else if (sz == GN)      bias = (const float*)d_in[i];
        else if (sz == 1 && ns < 3) scales[ns++] = (const float*)d_in[i];
    }
    const float* xs = scales[0];   // x_scale (first size-1 input)
    const float* ws = scales[1];   // w_scale (second size-1 input)
    float* out = (float*)d_out;

    {
        const int total = X_TOTAL8 + W_TOTAL8;
        quant_both_kernel<<<total / 256, 256>>>(x, wgt, xs, ws);
    }

    cudaFuncSetAttribute(gemm_kernel, cudaFuncAttributeMaxDynamicSharedMemorySize, SMEM_TOTAL);
    dim3 grid(GN / BN, GM / BM);   // (32, 64) = 2048 CTAs, 2/SM
    gemm_kernel<<<grid, THREADS, SMEM_TOTAL>>>(bias, xs, ws, out);
}

// round 16
// speedup vs baseline: 1.0671x; 1.0534x over previous
#include <cuda_runtime.h>
#include <cuda_bf16.h>
#include <cuda_fp8.h>
#include <cstdint>

// ============================================================================
// y[M,N] = fq(x*sx)[M,K] @ fq(w*sw)[N,K]^T / (sx*sw) + bias, bf16-rounded,
// stored as f32. fp8 mma.sync.m16n8k32 (bit-exact, R9+).
// R16: persistent CTAs, continuous chunk stream across tiles (no per-tile
// pipeline fill/drain, epilogue overlapped with next tile's loads, no wave
// tail), precomputed swizzled fragment offsets.
// ============================================================================
#define GM 8192
#define GN 4096
#define GK 4096

#define BM 128
#define BN 128
#define BK 128                     // fp8 bytes per K chunk
#define K_CHUNKS (GK / BK)         // 32
#define NTILES ((GM / BM) * (GN / BN))   // 2048
#define STAGES 3
#define THREADS 256

#define A_BYTES (BM * BK)          // 16384
#define B_BYTES (BN * BK)          // 16384
#define STAGE_BYTES (A_BYTES + B_BYTES)      // 32768
#define STAGE_SMEM (STAGES * STAGE_BYTES)    // 98304
#define SMEM_TOTAL (STAGE_SMEM + 64)         // + mbarriers; 2 CTAs/SM

__device__ __align__(128) unsigned char g_Aq[(size_t)GM * GK];
__device__ __align__(128) unsigned char g_Bq[(size_t)GN * GK];

// ============================================================================
// helpers
// ============================================================================
__device__ __forceinline__ uint32_t smem_to_u32(const void* p) {
    uint32_t a;
    asm("{ .reg .u64 t; cvta.to.shared.u64 t, %1; cvt.u32.u64 %0, t; }" : "=r"(a) : "l"(p));
    return a;
}
__device__ __forceinline__ void cp_async16(uint32_t dst_smem, const void* src) {
    asm volatile("cp.async.cg.shared.global [%0], [%1], 16;"
                 :: "r"(dst_smem), "l"(src) : "memory");
}

#define MBARRIER_INIT(addr, cnt) \
    asm volatile("mbarrier.init.shared.b64 [%0], %1;" \
                 :: "r"((uint32_t)(addr)), "r"((uint32_t)(cnt)) : "memory")
#define MBARRIER_ARRIVE(addr) \
    asm volatile("mbarrier.arrive.shared.b64 _, [%0];" :: "r"((uint32_t)(addr)) : "memory")
#define CP_ASYNC_MBAR_ARRIVE_NOINC(addr) \
    asm volatile("cp.async.mbarrier.arrive.noinc.shared.b64 [%0];" \
                 :: "r"((uint32_t)(addr)) : "memory")

#define MBAR_WAIT(mbar, parity) do { \
    uint32_t _m = (uint32_t)(mbar); \
    uint32_t _p = (uint32_t)(parity); \
    uint32_t _done; \
    asm volatile("{\n\t.reg .pred p;\n\t" \
        "mbarrier.try_wait.parity.acquire.cta.shared::cta.b64 p, [%1], %2;\n\t" \
        "selp.b32 %0, 1, 0, p;\n\t}" : "=r"(_done) : "r"(_m), "r"(_p) : "memory"); \
    if (!_done) { \
        asm volatile("{\n\t.reg .pred P1;\n\t" \
            "WL_%=:\n\t" \
            "mbarrier.try_wait.parity.acquire.cta.shared::cta.b64 P1, [%0], %1, 0x989680;\n\t" \
            "@P1 bra.uni WD_%=;\n\t" \
            "bra.uni WL_%=;\n\t" \
            "WD_%=:\n\t}" :: "r"(_m), "r"(_p) : "memory"); \
    } \
} while (0)

__device__ __forceinline__ void ldmatrix_x4(uint32_t& r0, uint32_t& r1,
                                            uint32_t& r2, uint32_t& r3, uint32_t addr) {
    asm volatile("ldmatrix.sync.aligned.m8n8.x4.shared.b16 {%0,%1,%2,%3}, [%4];"
                 : "=r"(r0), "=r"(r1), "=r"(r2), "=r"(r3) : "r"(addr));
}

__device__ __forceinline__ void mma_e4m3(float* d, const uint32_t* a,
                                         uint32_t b0, uint32_t b1) {
    asm volatile(
        "mma.sync.aligned.m16n8k32.row.col.f32.e4m3.e4m3.f32 "
        "{%0,%1,%2,%3}, {%4,%5,%6,%7}, {%8,%9}, {%0,%1,%2,%3};"
        : "+f"(d[0]), "+f"(d[1]), "+f"(d[2]), "+f"(d[3])
        : "r"(a[0]), "r"(a[1]), "r"(a[2]), "r"(a[3]), "r"(b0), "r"(b1));
}

// ----------------------------------------------------------------------------
// Exact reference fake-quant (E4M3). Bit-exact vs reference (R8-R15: rel=0).
// ----------------------------------------------------------------------------
__device__ __forceinline__ float fake_quant_e4m3(float y) {
    float yc = fminf(fmaxf(y, -448.0f), 448.0f);
    float mag = fabsf(yc);
    if (mag == 0.0f) return 0.0f;
    int e = (int)((__float_as_uint(mag) >> 23) & 0xFF) - 127;
    if (e < -6) e = -6;
    float stepinv = __int_as_float((uint32_t)(127 + 3 - e) << 23);  // 2^(3-e)
    float step    = __int_as_float((uint32_t)(127 - 3 + e) << 23);  // 2^(e-3)
    return rintf(yc * stepinv) * step;
}

// ============================================================================
// Merged quantization
// ============================================================================
#define X_TOTAL8 (GM * GK / 8)
#define W_TOTAL8 (GN * GK / 8)

__global__ void quant_both_kernel(const float* __restrict__ x,
                                  const float* __restrict__ wgt,
                                  const float* __restrict__ xs,
                                  const float* __restrict__ ws) {
    int idx = blockIdx.x * blockDim.x + threadIdx.x;
    const float* src;
    unsigned char* dst;
    float s;
    if (idx < X_TOTAL8) {
        src = x; dst = g_Aq; s = xs[0];
    } else {
        idx -= X_TOTAL8;
        if (idx >= W_TOTAL8) return;
        src = wgt; dst = g_Bq; s = ws[0];
    }
    size_t e0 = (size_t)idx * 8;
    float4 v0 = *reinterpret_cast<const float4*>(src + e0);
    float4 v1 = *reinterpret_cast<const float4*>(src + e0 + 4);
    float f[8] = {v0.x, v0.y, v0.z, v0.w, v1.x, v1.y, v1.z, v1.w};
    uint64_t out8 = 0;
#pragma unroll
    for (int i = 0; i < 8; i++) {
        float q = fake_quant_e4m3(f[i] * s);
        uint8_t b = __nv_cvt_float_to_fp8(q, __NV_SATFINITE, __NV_E4M3);
        out8 |= (uint64_t)b << (8 * i);
    }
    *reinterpret_cast<uint64_t*>(dst + e0) = out8;
}

// ============================================================================
// Persistent FP8 GEMM: each CTA streams chunks of its tile list through one
// continuous 3-stage mbarrier pipeline. 8 warps (32x64), 2 CTAs/SM.
// ============================================================================
__global__ void __launch_bounds__(THREADS, 2) gemm_kernel(
    const float* __restrict__ bias,
    const float* __restrict__ xs, const float* __restrict__ ws,
    float* __restrict__ out) {
    extern __shared__ __align__(128) char smem[];
    const uint32_t smem_base = smem_to_u32(smem);
    const uint32_t mbar_base = smem_base + STAGE_SMEM;
    const int tid = threadIdx.x;
    const int w = tid >> 5, l = tid & 31;
    const int warp_m = (w >> 1) * 32;
    const int warp_n = (w & 1) * 64;
    const int bid = blockIdx.x, gsz = gridDim.x;

    if (tid == 0) {
#pragma unroll
        for (int s = 0; s < STAGES; s++) {
            MBARRIER_INIT(mbar_base + 16 * s, THREADS);      // full[s]
            MBARRIER_INIT(mbar_base + 16 * s + 8, THREADS);  // empty[s]
        }
    }
    __syncthreads();

    const int myTiles = (NTILES - bid + gsz - 1) / gsz;
    const int L = myTiles * K_CHUNKS;       // my total chunk stream length

    // produce stream chunk p into stage s (use-index u for parity)
    auto produce = [&](int p, int s, int u) {
        const int ti = p >> 5, kc = p & 31;
        const int t = bid + ti * gsz;
        const int mt = t >> 5, nt = t & 31;   // 64 x 32 tile grid
        const unsigned char* Ag = g_Aq + (size_t)(mt * BM) * GK;
        const unsigned char* Bg = g_Bq + (size_t)(nt * BN) * GK;
        if (p >= STAGES) {
            MBAR_WAIT(mbar_base + 16 * s + 8, (u - 1) & 1);
        }
        const uint32_t sa = smem_base + s * STAGE_BYTES;
        const uint32_t sb = sa + A_BYTES;
#pragma unroll
        for (int i = 0; i < 4; i++) {
            int c = tid + i * THREADS;
            int row = c >> 3, cb = c & 7;
            cp_async16(sa + row * 128 + ((cb ^ (row & 7)) << 4),
                       Ag + (size_t)row * GK + kc * BK + cb * 16);
        }
#pragma unroll
        for (int i = 0; i < 4; i++) {
            int c = tid + i * THREADS;
            int row = c >> 3, cb = c & 7;
            cp_async16(sb + row * 128 + ((cb ^ (row & 7)) << 4),
                       Bg + (size_t)row * GK + kc * BK + cb * 16);
        }
        CP_ASYNC_MBAR_ARRIVE_NOINC(mbar_base + 16 * s);
    };

    // accumulators: 64 regs
    float d[2][8][4];
#pragma unroll
    for (int i = 0; i < 2; i++)
#pragma unroll
        for (int j = 0; j < 8; j++)
#pragma unroll
            for (int q = 0; q < 4; q++) d[i][j][q] = 0.0f;

    produce(0, 0, 0);
    produce(1, 1, 0);

    // precomputed swizzled fragment offsets (per thread, stage-independent)
    const int lr = l & 15, lk = l >> 4;
    const int rowA0 = (warp_m + lr) * 128;
    const int rowB0 = (warp_n + lr) * 128;
    const int rxA = (warp_m + lr) & 7;
    const int rxB = (warp_n + lr) & 7;
    int offA[4], offB[4];
#pragma unroll
    for (int ks = 0; ks < 4; ks++) {
        const int kg = ks * 2 + lk;
        offA[ks] = rowA0 + ((((kg ^ rxA) & 7)) << 4);
        offB[ks] = rowB0 + ((((kg ^ rxB) & 7)) << 4);
    }

    const float inv = 1.0f / (xs[0] * ws[0]);
    const int erow = warp_m + (l >> 2);          // tile-local epilogue row
    const int ecol = warp_n + 2 * (l & 3);       // tile-local epilogue col

    int s_cons = 0, u_cons = 0;
    int s_prod = 2, u_prod = 0;

#pragma unroll 1
    for (int p = 0; p < L; ++p) {
        if (p + 2 < L) {
            produce(p + 2, s_prod, u_prod);
            if (++s_prod == STAGES) { s_prod = 0; ++u_prod; }
        }

        MBAR_WAIT(mbar_base + 16 * s_cons, u_cons & 1);

        const uint32_t sa = smem_base + s_cons * STAGE_BYTES;
        const uint32_t sb = sa + A_BYTES;

#pragma unroll
        for (int ks = 0; ks < 4; ++ks) {
            uint32_t a[2][4], bf[4][4];
#pragma unroll
            for (int mi = 0; mi < 2; mi++)
                ldmatrix_x4(a[mi][0], a[mi][1], a[mi][2], a[mi][3],
                            sa + offA[ks] + mi * (16 * 128));
#pragma unroll
            for (int j = 0; j < 4; j++)
                ldmatrix_x4(bf[j][0], bf[j][1], bf[j][2], bf[j][3],
                            sb + offB[ks] + j * (16 * 128));
#pragma unroll
            for (int mi = 0; mi < 2; mi++)
#pragma unroll
                for (int nj = 0; nj < 8; nj++) {
                    const int j = nj >> 1, h = nj & 1;
                    mma_e4m3(d[mi][nj], a[mi], bf[j][h], bf[j][2 + h]);
                }
        }
        MBARRIER_ARRIVE(mbar_base + 16 * s_cons + 8);
        if (++s_cons == STAGES) { s_cons = 0; ++u_cons; }

        // ---- tile boundary: epilogue + accumulator reset ----
        if ((p & 31) == 31) {
            const int t = bid + (p >> 5) * gsz;
            const int mt = t >> 5, nt = t & 31;
            const int mrow = mt * BM + erow;
            const int ncol0 = nt * BN + ecol;
#pragma unroll
            for (int nj = 0; nj < 8; nj++) {
                const int n = ncol0 + nj * 8;
                const float b0 = bias[n];
                const float b1 = bias[n + 1];
#pragma unroll
                for (int mi = 0; mi < 2; mi++) {
                    const int m0 = mrow + mi * 16;
                    float f0 = __bfloat162float(__float2bfloat16_rn(d[mi][nj][0] * inv + b0));
                    float f1 = __bfloat162float(__float2bfloat16_rn(d[mi][nj][1] * inv + b1));
                    float f2 = __bfloat162float(__float2bfloat16_rn(d[mi][nj][2] * inv + b0));
                    float f3 = __bfloat162float(__float2bfloat16_rn(d[mi][nj][3] * inv + b1));
                    *reinterpret_cast<float2*>(out + (size_t)m0 * GN + n) = make_float2(f0, f1);
                    *reinterpret_cast<float2*>(out + (size_t)(m0 + 8) * GN + n) = make_float2(f2, f3);
                }
            }
#pragma unroll
            for (int i = 0; i < 2; i++)
#pragma unroll
                for (int j = 0; j < 8; j++)
#pragma unroll
                    for (int q = 0; q < 4; q++) d[i][j][q] = 0.0f;
        }
    }
}

// ============================================================================
// kernel_launch — inputs identified by element count
// ============================================================================
extern "C" void kernel_launch(void* const* d_in, const int* in_sizes, int n_in,
                              void* d_out, int out_size) {
    const float* x = nullptr;
    const float* wgt = nullptr;
    const float* bias = nullptr;
    const float* scales[3] = {nullptr, nullptr, nullptr};
    int ns = 0;
    for (int i = 0; i < n_in; i++) {
        const int sz = in_sizes[i];
        if (sz == GM * GK)      x    = (const float*)d_in[i];
        else if (sz == GN * GK) wgt  = (const float*)d_in[i];
        else if (sz == GN)      bias = (const float*)d_in[i];
        else if (sz == 1 && ns < 3) scales[ns++] = (const float*)d_in[i];
    }
    const float* xs = scales[0];
    const float* ws = scales[1];
    float* out = (float*)d_out;

    {
        const int total = X_TOTAL8 + W_TOTAL8;
        quant_both_kernel<<<total / 256, 256>>>(x, wgt, xs, ws);
    }

    int sms = 148;
    cudaDeviceGetAttribute(&sms, cudaDevAttrMultiProcessorCount, 0);
    int grid = 2 * sms;                       // persistent: 2 CTAs per SM
    if (grid > NTILES) grid = NTILES;

    cudaFuncSetAttribute(gemm_kernel, cudaFuncAttributeMaxDynamicSharedMemorySize, SMEM_TOTAL);
    gemm_kernel<<<grid, THREADS, SMEM_TOTAL>>>(bias, xs, ws, out);
}